// round 1
// baseline (speedup 1.0000x reference)
#include <cuda_runtime.h>
#include <math.h>

#define Bb 32
#define Hh 1024
#define Ss 512
#define Tt 32
#define N3 3072
#define NN 6144
#define KCH 128
#define KSPLIT 8
#define NT 128
#define NBLK (NN / NT)   // 48

// ---------------- device scratch ----------------
__device__ __align__(16) float g_wt[(size_t)Hh * NN];     // [k][n] transposed combined weights (w_ih | w_hh)
__device__ __align__(16) float g_bias[NN];                // (b_ih | b_hh)
__device__ __align__(16) float g_h[Bb * Hh];              // GRU hidden
__device__ __align__(16) float g_x[Bb * Hh];              // decoder input
__device__ __align__(16) float g_a[Bb * Ss];              // inputs . v2
__device__ __align__(16) float g_v1[Hh];                  // W1^T V
__device__ __align__(16) float g_v2[Hh];                  // W2^T V
__device__ __align__(16) float g_gbuf[(size_t)KSPLIT * Bb * NN]; // GEMM partials

// ---------------- prep kernels ----------------
__global__ void prep_init(const float* __restrict__ features) {
    int i = blockIdx.x * 1024 + threadIdx.x;
    g_h[i] = 0.f;
    g_x[i] = features[i];
}

// v1[d] = sum_h V[h]*W1[h,d] ; v2 with W2
__global__ void prep_v(const float* __restrict__ W1, const float* __restrict__ W2,
                       const float* __restrict__ V) {
    __shared__ float vs[Hh];
    int tid = threadIdx.x;
    for (int i = tid; i < Hh; i += 256) vs[i] = V[i];
    __syncthreads();
    int sel = blockIdx.x >> 2;          // 0 -> W1/v1, 1 -> W2/v2
    int d = (blockIdx.x & 3) * 256 + tid;
    const float* W = sel ? W2 : W1;
    float acc = 0.f;
    for (int h = 0; h < Hh; h++) acc = fmaf(vs[h], W[(size_t)h * Hh + d], acc);
    if (sel) g_v2[d] = acc; else g_v1[d] = acc;
}

// transpose weights into g_wt[k][n]; n<3072 -> w_ih, else w_hh
__global__ void prep_wt(const float* __restrict__ w_ih, const float* __restrict__ w_hh) {
    __shared__ float tile[32][33];
    int nb = blockIdx.x;   // NN/32 = 192
    int kb = blockIdx.y;   // H/32 = 32
    int tx = threadIdx.x;  // 32
    int ty = threadIdx.y;  // 8
    for (int i = ty; i < 32; i += 8) {
        int n = nb * 32 + i;
        int k = kb * 32 + tx;
        tile[i][tx] = (n < N3) ? w_ih[(size_t)n * Hh + k]
                               : w_hh[(size_t)(n - N3) * Hh + k];
    }
    __syncthreads();
    for (int i = ty; i < 32; i += 8) {
        int k = kb * 32 + i;
        int n = nb * 32 + tx;
        g_wt[(size_t)k * NN + n] = tile[tx][i];
    }
}

__global__ void prep_bias(const float* __restrict__ b_ih, const float* __restrict__ b_hh) {
    int i = blockIdx.x * 1024 + threadIdx.x;
    g_bias[i] = (i < N3) ? b_ih[i] : b_hh[i - N3];
}

// a[row] = inputs[row,:] . v2   (row = b*S + s), one warp per row
__global__ void prep_a(const float* __restrict__ inputs) {
    __shared__ float v2s[Hh];
    int tid = threadIdx.x;
    for (int i = tid; i < Hh; i += 256) v2s[i] = g_v2[i];
    __syncthreads();
    int warp = tid >> 5, lane = tid & 31;
    int row = blockIdx.x * 8 + warp;
    const float* r = inputs + (size_t)row * Hh;
    float acc = 0.f;
#pragma unroll
    for (int i = 0; i < 8; i++) {
        float4 x4 = *(const float4*)&r[(i * 32 + lane) * 4];
        float4 v4 = *(const float4*)&v2s[(i * 32 + lane) * 4];
        acc += x4.x * v4.x + x4.y * v4.y + x4.z * v4.z + x4.w * v4.w;
    }
#pragma unroll
    for (int o = 16; o > 0; o >>= 1) acc += __shfl_xor_sync(0xFFFFFFFFu, acc, o);
    if (lane == 0) g_a[row] = acc;
}

// ---------------- per-step GEMM: y[b,n] = A[b,:] . g_wt[:,n] (K-split partials) ----------------
// A = g_x for n<3072 (gi), g_h for n>=3072 (gh)
__global__ void __launch_bounds__(256) gru_gemm() {
    __shared__ __align__(16) float As[KCH][36];
    __shared__ __align__(16) float Ws[8][128];
    const int nb = blockIdx.x;
    const int kz = blockIdx.y;
    const int n0 = nb * NT;
    const int k0 = kz * KCH;
    const float* Ag = (n0 < N3) ? g_x : g_h;
    const int tid = threadIdx.x;
    const int tx = tid & 31;
    const int ty = tid >> 5;
    const int b0 = ty * 4;

    // stage A chunk transposed: As[k][b]
#pragma unroll
    for (int i = 0; i < (Bb * KCH) / 256; i++) {
        int idx = tid + i * 256;
        int bb = idx >> 7;       // KCH = 128
        int kk = idx & 127;
        As[kk][bb] = Ag[bb * Hh + k0 + kk];
    }

    float acc[4][4];
#pragma unroll
    for (int i = 0; i < 4; i++)
#pragma unroll
        for (int j = 0; j < 4; j++) acc[i][j] = 0.f;

    const int wkk = tid >> 5;
    const int wn4 = (tid & 31) * 4;

    for (int k8 = 0; k8 < KCH / 8; k8++) {
        __syncthreads();
        *(float4*)&Ws[wkk][wn4] =
            *(const float4*)&g_wt[(size_t)(k0 + k8 * 8 + wkk) * NN + n0 + wn4];
        __syncthreads();
#pragma unroll
        for (int kk = 0; kk < 8; kk++) {
            const float4 a4 = *(const float4*)&As[k8 * 8 + kk][b0];
            const float4 w4 = *(const float4*)&Ws[kk][tx * 4];
            float av[4] = {a4.x, a4.y, a4.z, a4.w};
#pragma unroll
            for (int i = 0; i < 4; i++) {
                acc[i][0] = fmaf(av[i], w4.x, acc[i][0]);
                acc[i][1] = fmaf(av[i], w4.y, acc[i][1]);
                acc[i][2] = fmaf(av[i], w4.z, acc[i][2]);
                acc[i][3] = fmaf(av[i], w4.w, acc[i][3]);
            }
        }
    }
#pragma unroll
    for (int i = 0; i < 4; i++) {
        float4 o = make_float4(acc[i][0], acc[i][1], acc[i][2], acc[i][3]);
        *(float4*)&g_gbuf[((size_t)(kz * Bb) + b0 + i) * NN + n0 + tx * 4] = o;
    }
}

// ---------------- per-step combine + score + argmax + gather ----------------
__global__ void __launch_bounds__(1024) gru_step(const float* __restrict__ inputs,
                                                 const float* __restrict__ mask,
                                                 float* __restrict__ probs, int t) {
    const int b = blockIdx.x;
    const int j = threadIdx.x;
    __shared__ float red[1024];
    __shared__ float sv[512];
    __shared__ int si[512];

    float gr = g_bias[j],        gz = g_bias[j + 1024], gn = g_bias[j + 2048];
    float hr = g_bias[j + 3072], hz = g_bias[j + 4096], hn = g_bias[j + 5120];
#pragma unroll
    for (int kz = 0; kz < KSPLIT; kz++) {
        const float* gb = g_gbuf + ((size_t)(kz * Bb) + b) * NN;
        gr += gb[j];        gz += gb[j + 1024]; gn += gb[j + 2048];
        hr += gb[j + 3072]; hz += gb[j + 4096]; hn += gb[j + 5120];
    }
    float hold = g_h[b * Hh + j];
    float r = 1.f / (1.f + expf(-(gr + hr)));
    float z = 1.f / (1.f + expf(-(gz + hz)));
    float nv = tanhf(gn + r * hn);
    float hnew = (1.f - z) * nv + z * hold;
    g_h[b * Hh + j] = hnew;

    // c = v1 . h_new
    red[j] = g_v1[j] * hnew;
    __syncthreads();
    for (int st = 512; st >= 1; st >>= 1) {
        if (j < st) red[j] += red[j + st];
        __syncthreads();
    }
    float c = red[0];

    // scores + argmax(scores+mask)
    if (j < Ss) {
        float sc = tanhf(c + g_a[b * Ss + j]);
        probs[((size_t)b * Tt + t) * Ss + j] = sc;
        sv[j] = sc + mask[b * Ss + j];
        si[j] = j;
    }
    __syncthreads();
    for (int st = 256; st >= 1; st >>= 1) {
        if (j < st) {
            float v = sv[j + st]; int ii = si[j + st];
            if (v > sv[j] || (v == sv[j] && ii < si[j])) { sv[j] = v; si[j] = ii; }
        }
        __syncthreads();
    }
    int idx = si[0];
    // gather next decoder input
    g_x[b * Hh + j] = inputs[((size_t)b * Ss + idx) * Hh + j];
}

// ---------------- context from step-0 scores ----------------
__global__ void __launch_bounds__(256) ctx_kernel(const float* __restrict__ inputs,
                                                  const float* __restrict__ mask,
                                                  const float* __restrict__ probs,
                                                  float* __restrict__ ctx) {
    const int b = blockIdx.x;
    const int hq = blockIdx.y;
    const int tid = threadIdx.x;
    __shared__ float p[Ss];
    __shared__ float red[256];

    for (int s = tid; s < Ss; s += 256)
        p[s] = probs[(size_t)b * Tt * Ss + s] + mask[b * Ss + s];
    __syncthreads();
    float m = -1e30f;
    for (int s = tid; s < Ss; s += 256) m = fmaxf(m, p[s]);
    red[tid] = m;
    __syncthreads();
    for (int st = 128; st >= 1; st >>= 1) {
        if (tid < st) red[tid] = fmaxf(red[tid], red[tid + st]);
        __syncthreads();
    }
    const float mx = red[0];
    __syncthreads();
    float sm = 0.f;
    for (int s = tid; s < Ss; s += 256) {
        float e = expf(p[s] - mx);
        p[s] = e;
        sm += e;
    }
    red[tid] = sm;
    __syncthreads();
    for (int st = 128; st >= 1; st >>= 1) {
        if (tid < st) red[tid] += red[tid + st];
        __syncthreads();
    }
    const float Z = red[0];
    __syncthreads();
    const int h = hq * 256 + tid;
    float acc = 0.f;
    for (int s = 0; s < Ss; s++)
        acc = fmaf(p[s], inputs[((size_t)b * Ss + s) * Hh + h], acc);
    ctx[b * Hh + h] = acc / Z;
}

// ---------------- launch ----------------
extern "C" void kernel_launch(void* const* d_in, const int* in_sizes, int n_in,
                              void* d_out, int out_size) {
    const float* inputs   = (const float*)d_in[0];
    const float* mask     = (const float*)d_in[1];
    // d_in[2] = inputs_embeds, unused (use_emb=False path)
    const float* features = (const float*)d_in[3];
    const float* w_ih     = (const float*)d_in[4];
    const float* b_ih     = (const float*)d_in[5];
    const float* w_hh     = (const float*)d_in[6];
    const float* b_hh     = (const float*)d_in[7];
    const float* W1       = (const float*)d_in[8];
    const float* W2       = (const float*)d_in[9];
    const float* V        = (const float*)d_in[10];

    float* out   = (float*)d_out;
    float* probs = out;                            // [B, T, S]
    float* ctx   = out + (size_t)Bb * Tt * Ss;     // [B, H]

    prep_init<<<Bb, 1024>>>(features);
    prep_v<<<8, 256>>>(W1, W2, V);
    prep_wt<<<dim3(NN / 32, Hh / 32), dim3(32, 8)>>>(w_ih, w_hh);
    prep_bias<<<NN / 1024, 1024>>>(b_ih, b_hh);
    prep_a<<<(Bb * Ss) / 8, 256>>>(inputs);

    for (int t = 0; t < Tt; t++) {
        gru_gemm<<<dim3(NBLK, KSPLIT), 256>>>();
        gru_step<<<Bb, 1024>>>(inputs, mask, probs, t);
    }
    ctx_kernel<<<dim3(Bb, 4), 256>>>(inputs, mask, probs, ctx);
}